// round 3
// baseline (speedup 1.0000x reference)
#include <cuda_runtime.h>
#include <cuda_fp16.h>

// ---------------------------------------------------------------------------
// ShiftedWindowAttention: B=32, H=W=64, C=256, HEADS=8, HD=32, WS=8, SHIFT=4
// Windows: 2048 total (32 batches x 64 windows), 64 tokens each.
// Pipeline: gather(fp16) -> QKV gemm (mma.sync fp16/fp32) -> per-window attn
//           -> out-proj gemm with merge/roll scatter.
// ---------------------------------------------------------------------------

#define WIN_TOT 2048
#define SCALE_F 0.17677669529663687f

// Scratch (allocation-free rule: __device__ globals)
__device__ __half g_xh [(size_t)WIN_TOT * 64 * 256];   // gathered x, fp16
__device__ __half g_q  [(size_t)WIN_TOT * 8 * 64 * 32];
__device__ __half g_k  [(size_t)WIN_TOT * 8 * 64 * 32];
__device__ __half g_v  [(size_t)WIN_TOT * 8 * 64 * 32];
__device__ __half g_att[(size_t)WIN_TOT * 64 * 256];   // attention output (win, tok, C)
__device__ __half g_wqkv[768 * 256];
__device__ __half g_wout[256 * 256];

// ---------------- mma / ldmatrix helpers ----------------
__device__ __forceinline__ void mma_16816(float c[4], const unsigned a[4],
                                          unsigned b0, unsigned b1) {
    asm volatile(
        "mma.sync.aligned.m16n8k16.row.col.f32.f16.f16.f32 "
        "{%0,%1,%2,%3}, {%4,%5,%6,%7}, {%8,%9}, {%0,%1,%2,%3};\n"
        : "+f"(c[0]), "+f"(c[1]), "+f"(c[2]), "+f"(c[3])
        : "r"(a[0]), "r"(a[1]), "r"(a[2]), "r"(a[3]), "r"(b0), "r"(b1));
}

__device__ __forceinline__ void ldsm_x4(unsigned r[4], const __half* p) {
    unsigned addr = (unsigned)__cvta_generic_to_shared(p);
    asm volatile("ldmatrix.sync.aligned.m8n8.x4.shared.b16 {%0,%1,%2,%3}, [%4];"
                 : "=r"(r[0]), "=r"(r[1]), "=r"(r[2]), "=r"(r[3]) : "r"(addr));
}
__device__ __forceinline__ void ldsm_x4_t(unsigned r[4], const __half* p) {
    unsigned addr = (unsigned)__cvta_generic_to_shared(p);
    asm volatile("ldmatrix.sync.aligned.m8n8.x4.trans.shared.b16 {%0,%1,%2,%3}, [%4];"
                 : "=r"(r[0]), "=r"(r[1]), "=r"(r[2]), "=r"(r[3]) : "r"(addr));
}

// A fragment (row-major M x K memory): matrices (m0,k0)(m0+8,k0)(m0,k0+8)(m0+8,k0+8)
__device__ __forceinline__ void ldfragA(unsigned r[4], const __half* t, int ld,
                                        int r0, int c0, int lane) {
    int lr = lane & 7, sel = lane >> 3;
    ldsm_x4(r, t + (r0 + lr + (sel & 1) * 8) * ld + c0 + ((sel >> 1) * 8));
}
// B fragment, memory (N x K) row-major (== K x N col-major): non-trans.
// Loads TWO n-tiles: regs {0,1} = ntile at n0, regs {2,3} = ntile at n0+8.
__device__ __forceinline__ void ldfragB(unsigned r[4], const __half* t, int ld,
                                        int n0, int k0, int lane) {
    int lr = lane & 7, sel = lane >> 3;
    ldsm_x4(r, t + (n0 + lr + ((sel >> 1) * 8)) * ld + k0 + ((sel & 1) * 8));
}
// B fragment, memory (K x N) row-major: trans. Two n-tiles (n0, n0+8).
__device__ __forceinline__ void ldfragBT(unsigned r[4], const __half* t, int ld,
                                         int k0, int n0, int lane) {
    int lr = lane & 7, sel = lane >> 3;
    ldsm_x4_t(r, t + (k0 + lr + ((sel & 1) * 8)) * ld + n0 + ((sel >> 1) * 8));
}

__device__ __forceinline__ unsigned packh2(float x, float y) {
    __half2 h = __floats2half2_rn(x, y);
    return *reinterpret_cast<unsigned*>(&h);
}

// ---------------- prep kernels ----------------
__global__ void prep_weights(const float* __restrict__ wqkv,
                             const float* __restrict__ wout) {
    int i = blockIdx.x * blockDim.x + threadIdx.x;
    if (i < 768 * 256) g_wqkv[i] = __float2half(wqkv[i]);
    if (i < 256 * 256) g_wout[i] = __float2half(wout[i]);
}

// roll(-4,-4) + window split + fp32->fp16
__global__ void gather_x(const float* __restrict__ x) {
    int win = blockIdx.x;
    int b = win >> 6, w = win & 63;
    int wy = w >> 3, wx = w & 7;
    const float* xb = x + (size_t)b * 4096 * 256;
    __half* dst = g_xh + (size_t)win * 64 * 256;
    for (int i = threadIdx.x; i < 64 * 64; i += blockDim.x) {
        int t = i >> 6, seg = i & 63;
        int ty = t >> 3, tx = t & 7;
        int gy = ((wy << 3) + ty + 4) & 63;
        int gx = ((wx << 3) + tx + 4) & 63;
        float4 v = reinterpret_cast<const float4*>(xb + (size_t)(gy * 64 + gx) * 256)[seg];
        __half2* d2 = reinterpret_cast<__half2*>(dst + t * 256);
        d2[seg * 2]     = __floats2half2_rn(v.x, v.y);
        d2[seg * 2 + 1] = __floats2half2_rn(v.z, v.w);
    }
}

// ---------------- QKV GEMM: M=131072, N=768, K=256 ----------------
// CTA tile 128x64, 8 warps (4m x 2n), warp tile 32x32, full-K in smem.
#define LDT 264
__global__ __launch_bounds__(256, 2) void qkv_gemm(const float* __restrict__ bqkv) {
    extern __shared__ __half sm[];
    __half* As = sm;               // [128][264]
    __half* Bs = sm + 128 * LDT;   // [64][264]
    int tid = threadIdx.x;
    int bm = blockIdx.x, bn = blockIdx.y;

    const int4* sA = reinterpret_cast<const int4*>(g_xh) + (size_t)bm * 128 * 32;
    #pragma unroll
    for (int i = tid; i < 4096; i += 256) {
        int row = i >> 5, seg = i & 31;
        *reinterpret_cast<int4*>(As + row * LDT + seg * 8) = sA[i];
    }
    const int4* sB = reinterpret_cast<const int4*>(g_wqkv) + (size_t)bn * 64 * 32;
    #pragma unroll
    for (int i = tid; i < 2048; i += 256) {
        int row = i >> 5, seg = i & 31;
        *reinterpret_cast<int4*>(Bs + row * LDT + seg * 8) = sB[i];
    }
    __syncthreads();

    int warp = tid >> 5, lane = tid & 31;
    int wm = warp >> 1, wn = warp & 1;
    float acc[2][4][4];
    #pragma unroll
    for (int i = 0; i < 2; i++)
        #pragma unroll
        for (int j = 0; j < 4; j++)
            #pragma unroll
            for (int e = 0; e < 4; e++) acc[i][j][e] = 0.f;

    const __half* Aw = As + (wm * 32) * LDT;
    const __half* Bw = Bs + (wn * 32) * LDT;
    #pragma unroll
    for (int kk = 0; kk < 16; kk++) {
        unsigned a0[4], a1[4], b0[4], b1[4];
        ldfragA(a0, Aw, LDT, 0,  kk * 16, lane);
        ldfragA(a1, Aw, LDT, 16, kk * 16, lane);
        ldfragB(b0, Bw, LDT, 0,  kk * 16, lane);
        ldfragB(b1, Bw, LDT, 16, kk * 16, lane);
        mma_16816(acc[0][0], a0, b0[0], b0[1]);
        mma_16816(acc[0][1], a0, b0[2], b0[3]);
        mma_16816(acc[0][2], a0, b1[0], b1[1]);
        mma_16816(acc[0][3], a0, b1[2], b1[3]);
        mma_16816(acc[1][0], a1, b0[0], b0[1]);
        mma_16816(acc[1][1], a1, b0[2], b0[3]);
        mma_16816(acc[1][2], a1, b1[0], b1[1]);
        mma_16816(acc[1][3], a1, b1[2], b1[3]);
    }

    int lr4 = lane >> 2, lc2 = (lane & 3) * 2;
    #pragma unroll
    for (int i = 0; i < 2; i++) {
        #pragma unroll
        for (int j = 0; j < 4; j++) {
            int col = bn * 64 + wn * 32 + j * 8 + lc2;   // 0..767
            int which = col >> 8;                        // 0=q 1=k 2=v
            int hd = (col >> 5) & 7, d = col & 31;
            float bb0 = bqkv[col], bb1 = bqkv[col + 1];
            __half* basep = (which == 0) ? g_q : ((which == 1) ? g_k : g_v);
            float scl = (which == 0) ? SCALE_F : 1.0f;
            #pragma unroll
            for (int r = 0; r < 2; r++) {
                int rowg = bm * 128 + wm * 32 + i * 16 + lr4 + r * 8;
                int win = rowg >> 6, tok = rowg & 63;
                float v0 = (acc[i][j][r * 2 + 0] + bb0) * scl;
                float v1 = (acc[i][j][r * 2 + 1] + bb1) * scl;
                *reinterpret_cast<__half2*>(basep + (((size_t)(win * 8 + hd) * 64 + tok) * 32 + d)) =
                    __floats2half2_rn(v0, v1);
            }
        }
    }
}

// ---------------- attention: 1 CTA = 1 window, warp = head ----------------
#define LDW 40
__global__ __launch_bounds__(256, 1) void attn_kernel(const float* __restrict__ pos_enc) {
    extern __shared__ unsigned char smraw[];
    __half* qs = reinterpret_cast<__half*>(smraw);          // 8 heads x [64][40]
    __half* ks = qs + 8 * 64 * LDW;
    __half* vs = ks + 8 * 64 * LDW;
    float* pe  = reinterpret_cast<float*>(vs + 8 * 64 * LDW); // [8][225]
    int*   rg  = reinterpret_cast<int*>(pe + 8 * 225);        // [64] region ids

    int tid = threadIdx.x;
    int win = blockIdx.x;
    int w = win & 63, wy = w >> 3, wx = w & 7;

    const int4* gq = reinterpret_cast<const int4*>(g_q + (size_t)win * 8 * 64 * 32);
    const int4* gk = reinterpret_cast<const int4*>(g_k + (size_t)win * 8 * 64 * 32);
    const int4* gv = reinterpret_cast<const int4*>(g_v + (size_t)win * 8 * 64 * 32);
    #pragma unroll 4
    for (int i = tid; i < 2048; i += 256) {
        int h = i >> 8, rem = i & 255;
        int t = rem >> 2, seg = rem & 3;
        int doff = (h * 64 + t) * LDW + seg * 8;
        *reinterpret_cast<int4*>(qs + doff) = gq[i];
        *reinterpret_cast<int4*>(ks + doff) = gk[i];
        *reinterpret_cast<int4*>(vs + doff) = gv[i];
    }
    for (int i = tid; i < 1800; i += 256) pe[i] = pos_enc[i];
    if (tid < 64) {
        int ty = tid >> 3, tx = tid & 7;
        int ry = (wy == 7) ? ((ty < 4) ? 1 : 2) : 0;
        int rx = (wx == 7) ? ((tx < 4) ? 1 : 2) : 0;
        rg[tid] = ry * 3 + rx;
    }
    __syncthreads();

    int warp = tid >> 5, lane = tid & 31, h = warp;
    const __half* qh = qs + h * 64 * LDW;
    const __half* kh = ks + h * 64 * LDW;
    const __half* vh = vs + h * 64 * LDW;
    const float* peh = pe + h * 225;
    int lr4 = lane >> 2, lc2 = (lane & 3) * 2;

    for (int s = 0; s < 4; s++) {
        float sa[8][4];
        #pragma unroll
        for (int nt = 0; nt < 8; nt++)
            #pragma unroll
            for (int e = 0; e < 4; e++) sa[nt][e] = 0.f;

        unsigned qa0[4], qa1[4];
        ldfragA(qa0, qh, LDW, s * 16, 0,  lane);
        ldfragA(qa1, qh, LDW, s * 16, 16, lane);
        #pragma unroll
        for (int np = 0; np < 4; np++) {
            unsigned kb0[4], kb1[4];
            ldfragB(kb0, kh, LDW, np * 16, 0,  lane);
            ldfragB(kb1, kh, LDW, np * 16, 16, lane);
            mma_16816(sa[2 * np],     qa0, kb0[0], kb0[1]);
            mma_16816(sa[2 * np + 1], qa0, kb0[2], kb0[3]);
            mma_16816(sa[2 * np],     qa1, kb1[0], kb1[1]);
            mma_16816(sa[2 * np + 1], qa1, kb1[2], kb1[3]);
        }

        // bias + shift-mask + softmax (rows q0=s*16+lr4 and q1=q0+8)
        int q0 = s * 16 + lr4, q1 = q0 + 8;
        int qy0 = q0 >> 3, qx0 = q0 & 7, qy1 = q1 >> 3, qx1 = q1 & 7;
        int r0 = rg[q0], r1 = rg[q1];
        float m0 = -1e30f, m1 = -1e30f;
        #pragma unroll
        for (int nt = 0; nt < 8; nt++) {
            #pragma unroll
            for (int e = 0; e < 2; e++) {
                int kc = nt * 8 + lc2 + e;
                int ky = kc >> 3, kx = kc & 7;
                int rk = rg[kc];
                float v = sa[nt][e] + peh[(qy0 - ky + 7) * 15 + (qx0 - kx + 7)];
                v = (rk != r0) ? -1e30f : v;
                sa[nt][e] = v; m0 = fmaxf(m0, v);
                float u = sa[nt][e + 2] + peh[(qy1 - ky + 7) * 15 + (qx1 - kx + 7)];
                u = (rk != r1) ? -1e30f : u;
                sa[nt][e + 2] = u; m1 = fmaxf(m1, u);
            }
        }
        m0 = fmaxf(m0, __shfl_xor_sync(0xffffffffu, m0, 1));
        m0 = fmaxf(m0, __shfl_xor_sync(0xffffffffu, m0, 2));
        m1 = fmaxf(m1, __shfl_xor_sync(0xffffffffu, m1, 1));
        m1 = fmaxf(m1, __shfl_xor_sync(0xffffffffu, m1, 2));
        float l0 = 0.f, l1 = 0.f;
        #pragma unroll
        for (int nt = 0; nt < 8; nt++) {
            #pragma unroll
            for (int e = 0; e < 2; e++) {
                float p = __expf(sa[nt][e] - m0);     sa[nt][e] = p;     l0 += p;
                float q_ = __expf(sa[nt][e + 2] - m1); sa[nt][e + 2] = q_; l1 += q_;
            }
        }
        l0 += __shfl_xor_sync(0xffffffffu, l0, 1);
        l0 += __shfl_xor_sync(0xffffffffu, l0, 2);
        l1 += __shfl_xor_sync(0xffffffffu, l1, 1);
        l1 += __shfl_xor_sync(0xffffffffu, l1, 2);
        float il0 = 1.0f / l0, il1 = 1.0f / l1;

        // O = P @ V  (unnormalized; divide by l at the end)
        float oa[4][4];
        #pragma unroll
        for (int j = 0; j < 4; j++)
            #pragma unroll
            for (int e = 0; e < 4; e++) oa[j][e] = 0.f;
        #pragma unroll
        for (int ksx = 0; ksx < 4; ksx++) {
            unsigned pa[4];
            pa[0] = packh2(sa[2 * ksx][0],     sa[2 * ksx][1]);
            pa[1] = packh2(sa[2 * ksx][2],     sa[2 * ksx][3]);
            pa[2] = packh2(sa[2 * ksx + 1][0], sa[2 * ksx + 1][1]);
            pa[3] = packh2(sa[2 * ksx + 1][2], sa[2 * ksx + 1][3]);
            unsigned vb[4];
            ldfragBT(vb, vh, LDW, ksx * 16, 0, lane);
            mma_16816(oa[0], pa, vb[0], vb[1]);
            mma_16816(oa[1], pa, vb[2], vb[3]);
            ldfragBT(vb, vh, LDW, ksx * 16, 16, lane);
            mma_16816(oa[2], pa, vb[0], vb[1]);
            mma_16816(oa[3], pa, vb[2], vb[3]);
        }
        #pragma unroll
        for (int j = 0; j < 4; j++) {
            int d = j * 8 + lc2;
            __half2 w0 = __floats2half2_rn(oa[j][0] * il0, oa[j][1] * il0);
            __half2 w1 = __floats2half2_rn(oa[j][2] * il1, oa[j][3] * il1);
            *reinterpret_cast<__half2*>(g_att + ((size_t)(win * 64 + q0) * 256) + h * 32 + d) = w0;
            *reinterpret_cast<__half2*>(g_att + ((size_t)(win * 64 + q1) * 256) + h * 32 + d) = w1;
        }
    }
}

// ---------------- out proj: M=131072, N=256, K=256, merge+roll scatter ----
__global__ __launch_bounds__(256, 2) void out_gemm(const float* __restrict__ bout,
                                                   float* __restrict__ out) {
    extern __shared__ __half sm[];
    __half* As = sm;
    __half* Bs = sm + 128 * LDT;
    int tid = threadIdx.x;
    int bm = blockIdx.x, bn = blockIdx.y;

    const int4* sA = reinterpret_cast<const int4*>(g_att) + (size_t)bm * 128 * 32;
    #pragma unroll
    for (int i = tid; i < 4096; i += 256) {
        int row = i >> 5, seg = i & 31;
        *reinterpret_cast<int4*>(As + row * LDT + seg * 8) = sA[i];
    }
    const int4* sB = reinterpret_cast<const int4*>(g_wout) + (size_t)bn * 64 * 32;
    #pragma unroll
    for (int i = tid; i < 2048; i += 256) {
        int row = i >> 5, seg = i & 31;
        *reinterpret_cast<int4*>(Bs + row * LDT + seg * 8) = sB[i];
    }
    __syncthreads();

    int warp = tid >> 5, lane = tid & 31;
    int wm = warp >> 1, wn = warp & 1;
    float acc[2][4][4];
    #pragma unroll
    for (int i = 0; i < 2; i++)
        #pragma unroll
        for (int j = 0; j < 4; j++)
            #pragma unroll
            for (int e = 0; e < 4; e++) acc[i][j][e] = 0.f;

    const __half* Aw = As + (wm * 32) * LDT;
    const __half* Bw = Bs + (wn * 32) * LDT;
    #pragma unroll
    for (int kk = 0; kk < 16; kk++) {
        unsigned a0[4], a1[4], b0[4], b1[4];
        ldfragA(a0, Aw, LDT, 0,  kk * 16, lane);
        ldfragA(a1, Aw, LDT, 16, kk * 16, lane);
        ldfragB(b0, Bw, LDT, 0,  kk * 16, lane);
        ldfragB(b1, Bw, LDT, 16, kk * 16, lane);
        mma_16816(acc[0][0], a0, b0[0], b0[1]);
        mma_16816(acc[0][1], a0, b0[2], b0[3]);
        mma_16816(acc[0][2], a0, b1[0], b1[1]);
        mma_16816(acc[0][3], a0, b1[2], b1[3]);
        mma_16816(acc[1][0], a1, b0[0], b0[1]);
        mma_16816(acc[1][1], a1, b0[2], b0[3]);
        mma_16816(acc[1][2], a1, b1[0], b1[1]);
        mma_16816(acc[1][3], a1, b1[2], b1[3]);
    }

    int lr4 = lane >> 2, lc2 = (lane & 3) * 2;
    #pragma unroll
    for (int i = 0; i < 2; i++) {
        #pragma unroll
        for (int j = 0; j < 4; j++) {
            int col = bn * 64 + wn * 32 + j * 8 + lc2;   // channel
            float bb0 = bout[col], bb1 = bout[col + 1];
            #pragma unroll
            for (int r = 0; r < 2; r++) {
                int rowg = bm * 128 + wm * 32 + i * 16 + lr4 + r * 8;
                int win = rowg >> 6, tok = rowg & 63;
                int b = win >> 6, w = win & 63;
                int wy = w >> 3, wx = w & 7;
                int ty = tok >> 3, tx = tok & 7;
                int gy = ((wy << 3) + ty + 4) & 63;
                int gx = ((wx << 3) + tx + 4) & 63;
                float2 v;
                v.x = acc[i][j][r * 2 + 0] + bb0;
                v.y = acc[i][j][r * 2 + 1] + bb1;
                *reinterpret_cast<float2*>(out + ((size_t)(b * 4096 + gy * 64 + gx)) * 256 + col) = v;
            }
        }
    }
}

// ---------------- launch ----------------
extern "C" void kernel_launch(void* const* d_in, const int* in_sizes, int n_in,
                              void* d_out, int out_size) {
    const float* x     = (const float*)d_in[0];
    const float* wqkv  = (const float*)d_in[1];
    const float* bqkv  = (const float*)d_in[2];
    const float* wout  = (const float*)d_in[3];
    const float* bout  = (const float*)d_in[4];
    const float* penc  = (const float*)d_in[5];
    float* out = (float*)d_out;

    const int SMEM_GEMM = (128 + 64) * LDT * 2;                    // 101376 B
    const int SMEM_ATTN = 3 * 8 * 64 * LDW * 2 + 8 * 225 * 4 + 64 * 4;  // 130336 B
    cudaFuncSetAttribute((const void*)qkv_gemm,  cudaFuncAttributeMaxDynamicSharedMemorySize, SMEM_GEMM);
    cudaFuncSetAttribute((const void*)out_gemm,  cudaFuncAttributeMaxDynamicSharedMemorySize, SMEM_GEMM);
    cudaFuncSetAttribute((const void*)attn_kernel, cudaFuncAttributeMaxDynamicSharedMemorySize, SMEM_ATTN);

    prep_weights<<<768, 256>>>(wqkv, wout);
    gather_x<<<WIN_TOT, 256>>>(x);
    qkv_gemm<<<dim3(1024, 12), 256, SMEM_GEMM>>>(bqkv);
    attn_kernel<<<WIN_TOT, 256, SMEM_ATTN>>>(penc);
    out_gemm<<<dim3(1024, 4), 256, SMEM_GEMM>>>(bout, out);
}

// round 4
// speedup vs baseline: 1.1528x; 1.1528x over previous
#include <cuda_runtime.h>
#include <cuda_fp16.h>

// ---------------------------------------------------------------------------
// ShiftedWindowAttention: B=32, H=W=64, C=256, HEADS=8, HD=32, WS=8, SHIFT=4
// R3: qkv/out gemms -> 128x256 CTA tiles, cp.async double-buffer, L2-friendly
//     grid order; attn -> 512 threads (2 warps/head).
// ---------------------------------------------------------------------------

#define WIN_TOT 2048
#define SCALE_F 0.17677669529663687f

__device__ __half g_xh [(size_t)WIN_TOT * 64 * 256];
__device__ __half g_q  [(size_t)WIN_TOT * 8 * 64 * 32];
__device__ __half g_k  [(size_t)WIN_TOT * 8 * 64 * 32];
__device__ __half g_v  [(size_t)WIN_TOT * 8 * 64 * 32];
__device__ __half g_att[(size_t)WIN_TOT * 64 * 256];
__device__ __half g_wqkv[768 * 256];
__device__ __half g_wout[256 * 256];

// ---------------- mma / ldmatrix helpers ----------------
__device__ __forceinline__ void mma_16816(float c[4], const unsigned a[4],
                                          unsigned b0, unsigned b1) {
    asm volatile(
        "mma.sync.aligned.m16n8k16.row.col.f32.f16.f16.f32 "
        "{%0,%1,%2,%3}, {%4,%5,%6,%7}, {%8,%9}, {%0,%1,%2,%3};\n"
        : "+f"(c[0]), "+f"(c[1]), "+f"(c[2]), "+f"(c[3])
        : "r"(a[0]), "r"(a[1]), "r"(a[2]), "r"(a[3]), "r"(b0), "r"(b1));
}
__device__ __forceinline__ void ldsm_x4(unsigned r[4], const __half* p) {
    unsigned addr = (unsigned)__cvta_generic_to_shared(p);
    asm volatile("ldmatrix.sync.aligned.m8n8.x4.shared.b16 {%0,%1,%2,%3}, [%4];"
                 : "=r"(r[0]), "=r"(r[1]), "=r"(r[2]), "=r"(r[3]) : "r"(addr));
}
__device__ __forceinline__ void ldsm_x4_t(unsigned r[4], const __half* p) {
    unsigned addr = (unsigned)__cvta_generic_to_shared(p);
    asm volatile("ldmatrix.sync.aligned.m8n8.x4.trans.shared.b16 {%0,%1,%2,%3}, [%4];"
                 : "=r"(r[0]), "=r"(r[1]), "=r"(r[2]), "=r"(r[3]) : "r"(addr));
}
__device__ __forceinline__ void ldfragA(unsigned r[4], const __half* t, int ld,
                                        int r0, int c0, int lane) {
    int lr = lane & 7, sel = lane >> 3;
    ldsm_x4(r, t + (r0 + lr + (sel & 1) * 8) * ld + c0 + ((sel >> 1) * 8));
}
__device__ __forceinline__ void ldfragB(unsigned r[4], const __half* t, int ld,
                                        int n0, int k0, int lane) {
    int lr = lane & 7, sel = lane >> 3;
    ldsm_x4(r, t + (n0 + lr + ((sel >> 1) * 8)) * ld + k0 + ((sel & 1) * 8));
}
__device__ __forceinline__ void ldfragBT(unsigned r[4], const __half* t, int ld,
                                         int k0, int n0, int lane) {
    int lr = lane & 7, sel = lane >> 3;
    ldsm_x4_t(r, t + (k0 + lr + ((sel & 1) * 8)) * ld + n0 + ((sel >> 1) * 8));
}
__device__ __forceinline__ unsigned packh2(float x, float y) {
    __half2 h = __floats2half2_rn(x, y);
    return *reinterpret_cast<unsigned*>(&h);
}
__device__ __forceinline__ void cp16(void* s, const void* g) {
    unsigned sa = (unsigned)__cvta_generic_to_shared(s);
    asm volatile("cp.async.cg.shared.global [%0], [%1], 16;" :: "r"(sa), "l"(g));
}
__device__ __forceinline__ void cp_commit() {
    asm volatile("cp.async.commit_group;");
}

// ---------------- prep kernels ----------------
__global__ void prep_weights(const float* __restrict__ wqkv,
                             const float* __restrict__ wout) {
    int i = blockIdx.x * blockDim.x + threadIdx.x;
    if (i < 768 * 256) g_wqkv[i] = __float2half(wqkv[i]);
    if (i < 256 * 256) g_wout[i] = __float2half(wout[i]);
}

__global__ void gather_x(const float* __restrict__ x) {
    int win = blockIdx.x;
    int b = win >> 6, w = win & 63;
    int wy = w >> 3, wx = w & 7;
    const float* xb = x + (size_t)b * 4096 * 256;
    __half* dst = g_xh + (size_t)win * 64 * 256;
    for (int i = threadIdx.x; i < 64 * 64; i += blockDim.x) {
        int t = i >> 6, seg = i & 63;
        int ty = t >> 3, tx = t & 7;
        int gy = ((wy << 3) + ty + 4) & 63;
        int gx = ((wx << 3) + tx + 4) & 63;
        float4 v = reinterpret_cast<const float4*>(xb + (size_t)(gy * 64 + gx) * 256)[seg];
        __half2* d2 = reinterpret_cast<__half2*>(dst + t * 256);
        d2[seg * 2]     = __floats2half2_rn(v.x, v.y);
        d2[seg * 2 + 1] = __floats2half2_rn(v.z, v.w);
    }
}

// ---------------- big GEMM core: CTA tile 128(M) x 256(N), K=256 split 2 ----
#define LDT2 136   // 128 + 8 halves
// smem per stage: A 128*136, B 256*136 halves
#define A_ST (128 * LDT2)
#define B_ST (256 * LDT2)
#define SMEM_GEMM2 ((2 * A_ST + 2 * B_ST) * 2)   // 208896 bytes

// loads one K-half (st) of A (from srcA, row stride 256) and B (srcB)
__device__ __forceinline__ void load_stage(__half* As, __half* Bs,
                                           const __half* srcA, const __half* srcB,
                                           int st, int tid) {
    #pragma unroll
    for (int i = tid; i < 2048; i += 256) {          // A: 128 rows x 16 segs
        int row = i >> 4, seg = i & 15;
        cp16(As + row * LDT2 + seg * 8, srcA + row * 256 + st * 128 + seg * 8);
    }
    #pragma unroll
    for (int i = tid; i < 4096; i += 256) {          // B: 256 rows x 16 segs
        int row = i >> 4, seg = i & 15;
        cp16(Bs + row * LDT2 + seg * 8, srcB + row * 256 + st * 128 + seg * 8);
    }
    cp_commit();
}

__device__ __forceinline__ void gemm_mainloop(float acc[2][16][4],
                                              const __half* As, const __half* Bs,
                                              int wm, int wn, int lane) {
    #pragma unroll
    for (int i = 0; i < 2; i++)
        #pragma unroll
        for (int j = 0; j < 16; j++)
            #pragma unroll
            for (int e = 0; e < 4; e++) acc[i][j][e] = (acc == acc) ? acc[i][j][e] : 0.f;
    #pragma unroll
    for (int st = 0; st < 2; st++) {
        if (st == 0) { asm volatile("cp.async.wait_group 1;"); }
        else         { asm volatile("cp.async.wait_group 0;"); }
        __syncthreads();
        const __half* Aw = As + st * A_ST + (wm * 32) * LDT2;
        const __half* Bw = Bs + st * B_ST + (wn * 128) * LDT2;
        #pragma unroll
        for (int kk = 0; kk < 8; kk++) {
            unsigned a0[4], a1[4];
            ldfragA(a0, Aw, LDT2, 0,  kk * 16, lane);
            ldfragA(a1, Aw, LDT2, 16, kk * 16, lane);
            #pragma unroll
            for (int j = 0; j < 8; j++) {
                unsigned b[4];
                ldfragB(b, Bw, LDT2, j * 16, kk * 16, lane);
                mma_16816(acc[0][2 * j],     a0, b[0], b[1]);
                mma_16816(acc[0][2 * j + 1], a0, b[2], b[3]);
                mma_16816(acc[1][2 * j],     a1, b[0], b[1]);
                mma_16816(acc[1][2 * j + 1], a1, b[2], b[3]);
            }
        }
        __syncthreads();
    }
}

// ---------------- QKV GEMM: grid (3, 1024); bn selects q/k/v ----------------
__global__ __launch_bounds__(256, 1) void qkv_gemm(const float* __restrict__ bqkv) {
    extern __shared__ __half sm[];
    __half* As = sm;
    __half* Bs = sm + 2 * A_ST;
    int tid = threadIdx.x;
    int bn = blockIdx.x, bm = blockIdx.y;

    const __half* srcA = g_xh + (size_t)bm * 128 * 256;
    const __half* srcB = g_wqkv + (size_t)bn * 256 * 256;
    load_stage(As, Bs, srcA, srcB, 0, tid);
    load_stage(As + A_ST, Bs + B_ST, srcA, srcB, 1, tid);

    int warp = tid >> 5, lane = tid & 31;
    int wm = warp >> 1, wn = warp & 1;
    float acc[2][16][4];
    #pragma unroll
    for (int i = 0; i < 2; i++)
        #pragma unroll
        for (int j = 0; j < 16; j++)
            #pragma unroll
            for (int e = 0; e < 4; e++) acc[i][j][e] = 0.f;

    gemm_mainloop(acc, As, Bs, wm, wn, lane);

    __half* basep = (bn == 0) ? g_q : ((bn == 1) ? g_k : g_v);
    float scl = (bn == 0) ? SCALE_F : 1.0f;
    int lr4 = lane >> 2, lc2 = (lane & 3) * 2;
    #pragma unroll
    for (int i = 0; i < 2; i++) {
        #pragma unroll
        for (int j = 0; j < 16; j++) {
            int col = wn * 128 + j * 8 + lc2;        // 0..255 within chunk
            int hd = col >> 5, d = col & 31;
            float bb0 = bqkv[bn * 256 + col], bb1 = bqkv[bn * 256 + col + 1];
            #pragma unroll
            for (int r = 0; r < 2; r++) {
                int rowg = bm * 128 + wm * 32 + i * 16 + lr4 + r * 8;
                int win = rowg >> 6, tok = rowg & 63;
                float v0 = (acc[i][j][r * 2 + 0] + bb0) * scl;
                float v1 = (acc[i][j][r * 2 + 1] + bb1) * scl;
                *reinterpret_cast<__half2*>(basep + (((size_t)(win * 8 + hd) * 64 + tok) * 32 + d)) =
                    __floats2half2_rn(v0, v1);
            }
        }
    }
}

// ---------------- attention: 1 CTA = 1 window, 16 warps, 2 warps/head ------
#define LDW 40
__global__ __launch_bounds__(512, 1) void attn_kernel(const float* __restrict__ pos_enc) {
    extern __shared__ unsigned char smraw[];
    __half* qs = reinterpret_cast<__half*>(smraw);
    __half* ks = qs + 8 * 64 * LDW;
    __half* vs = ks + 8 * 64 * LDW;
    float* pe  = reinterpret_cast<float*>(vs + 8 * 64 * LDW);
    int*   rg  = reinterpret_cast<int*>(pe + 8 * 225);

    int tid = threadIdx.x;
    int win = blockIdx.x;
    int w = win & 63, wy = w >> 3, wx = w & 7;

    const int4* gq = reinterpret_cast<const int4*>(g_q + (size_t)win * 8 * 64 * 32);
    const int4* gk = reinterpret_cast<const int4*>(g_k + (size_t)win * 8 * 64 * 32);
    const int4* gv = reinterpret_cast<const int4*>(g_v + (size_t)win * 8 * 64 * 32);
    #pragma unroll 2
    for (int i = tid; i < 2048; i += 512) {
        int h = i >> 8, rem = i & 255;
        int t = rem >> 2, seg = rem & 3;
        int doff = (h * 64 + t) * LDW + seg * 8;
        *reinterpret_cast<int4*>(qs + doff) = gq[i];
        *reinterpret_cast<int4*>(ks + doff) = gk[i];
        *reinterpret_cast<int4*>(vs + doff) = gv[i];
    }
    for (int i = tid; i < 1800; i += 512) pe[i] = pos_enc[i];
    if (tid < 64) {
        int ty = tid >> 3, tx = tid & 7;
        int ry = (wy == 7) ? ((ty < 4) ? 1 : 2) : 0;
        int rx = (wx == 7) ? ((tx < 4) ? 1 : 2) : 0;
        rg[tid] = ry * 3 + rx;
    }
    __syncthreads();

    int warp = tid >> 5, lane = tid & 31;
    int h = warp >> 1, half = warp & 1;
    const __half* qh = qs + h * 64 * LDW;
    const __half* kh = ks + h * 64 * LDW;
    const __half* vh = vs + h * 64 * LDW;
    const float* peh = pe + h * 225;
    int lr4 = lane >> 2, lc2 = (lane & 3) * 2;

    for (int s = 2 * half; s < 2 * half + 2; s++) {
        float sa[8][4];
        #pragma unroll
        for (int nt = 0; nt < 8; nt++)
            #pragma unroll
            for (int e = 0; e < 4; e++) sa[nt][e] = 0.f;

        unsigned qa0[4], qa1[4];
        ldfragA(qa0, qh, LDW, s * 16, 0,  lane);
        ldfragA(qa1, qh, LDW, s * 16, 16, lane);
        #pragma unroll
        for (int np = 0; np < 4; np++) {
            unsigned kb0[4], kb1[4];
            ldfragB(kb0, kh, LDW, np * 16, 0,  lane);
            ldfragB(kb1, kh, LDW, np * 16, 16, lane);
            mma_16816(sa[2 * np],     qa0, kb0[0], kb0[1]);
            mma_16816(sa[2 * np + 1], qa0, kb0[2], kb0[3]);
            mma_16816(sa[2 * np],     qa1, kb1[0], kb1[1]);
            mma_16816(sa[2 * np + 1], qa1, kb1[2], kb1[3]);
        }

        int q0 = s * 16 + lr4, q1 = q0 + 8;
        int qy0 = q0 >> 3, qx0 = q0 & 7, qy1 = q1 >> 3, qx1 = q1 & 7;
        int r0 = rg[q0], r1 = rg[q1];
        float m0 = -1e30f, m1 = -1e30f;
        #pragma unroll
        for (int nt = 0; nt < 8; nt++) {
            #pragma unroll
            for (int e = 0; e < 2; e++) {
                int kc = nt * 8 + lc2 + e;
                int ky = kc >> 3, kx = kc & 7;
                int rk = rg[kc];
                float v = sa[nt][e] + peh[(qy0 - ky + 7) * 15 + (qx0 - kx + 7)];
                v = (rk != r0) ? -1e30f : v;
                sa[nt][e] = v; m0 = fmaxf(m0, v);
                float u = sa[nt][e + 2] + peh[(qy1 - ky + 7) * 15 + (qx1 - kx + 7)];
                u = (rk != r1) ? -1e30f : u;
                sa[nt][e + 2] = u; m1 = fmaxf(m1, u);
            }
        }
        m0 = fmaxf(m0, __shfl_xor_sync(0xffffffffu, m0, 1));
        m0 = fmaxf(m0, __shfl_xor_sync(0xffffffffu, m0, 2));
        m1 = fmaxf(m1, __shfl_xor_sync(0xffffffffu, m1, 1));
        m1 = fmaxf(m1, __shfl_xor_sync(0xffffffffu, m1, 2));
        float l0 = 0.f, l1 = 0.f;
        #pragma unroll
        for (int nt = 0; nt < 8; nt++) {
            #pragma unroll
            for (int e = 0; e < 2; e++) {
                float p = __expf(sa[nt][e] - m0);      sa[nt][e] = p;      l0 += p;
                float q_ = __expf(sa[nt][e + 2] - m1); sa[nt][e + 2] = q_; l1 += q_;
            }
        }
        l0 += __shfl_xor_sync(0xffffffffu, l0, 1);
        l0 += __shfl_xor_sync(0xffffffffu, l0, 2);
        l1 += __shfl_xor_sync(0xffffffffu, l1, 1);
        l1 += __shfl_xor_sync(0xffffffffu, l1, 2);
        float il0 = 1.0f / l0, il1 = 1.0f / l1;

        float oa[4][4];
        #pragma unroll
        for (int j = 0; j < 4; j++)
            #pragma unroll
            for (int e = 0; e < 4; e++) oa[j][e] = 0.f;
        #pragma unroll
        for (int ksx = 0; ksx < 4; ksx++) {
            unsigned pa[4];
            pa[0] = packh2(sa[2 * ksx][0],     sa[2 * ksx][1]);
            pa[1] = packh2(sa[2 * ksx][2],     sa[2 * ksx][3]);
            pa[2] = packh2(sa[2 * ksx + 1][0], sa[2 * ksx + 1][1]);
            pa[3] = packh2(sa[2 * ksx + 1][2], sa[2 * ksx + 1][3]);
            unsigned vb[4];
            ldfragBT(vb, vh, LDW, ksx * 16, 0, lane);
            mma_16816(oa[0], pa, vb[0], vb[1]);
            mma_16816(oa[1], pa, vb[2], vb[3]);
            ldfragBT(vb, vh, LDW, ksx * 16, 16, lane);
            mma_16816(oa[2], pa, vb[0], vb[1]);
            mma_16816(oa[3], pa, vb[2], vb[3]);
        }
        #pragma unroll
        for (int j = 0; j < 4; j++) {
            int d = j * 8 + lc2;
            __half2 w0 = __floats2half2_rn(oa[j][0] * il0, oa[j][1] * il0);
            __half2 w1 = __floats2half2_rn(oa[j][2] * il1, oa[j][3] * il1);
            *reinterpret_cast<__half2*>(g_att + ((size_t)(win * 64 + q0) * 256) + h * 32 + d) = w0;
            *reinterpret_cast<__half2*>(g_att + ((size_t)(win * 64 + q1) * 256) + h * 32 + d) = w1;
        }
    }
}

// ---------------- out proj: 128x256 tile, single N pass, scatter -----------
__global__ __launch_bounds__(256, 1) void out_gemm(const float* __restrict__ bout,
                                                   float* __restrict__ out) {
    extern __shared__ __half sm[];
    __half* As = sm;
    __half* Bs = sm + 2 * A_ST;
    int tid = threadIdx.x;
    int bm = blockIdx.x;

    const __half* srcA = g_att + (size_t)bm * 128 * 256;
    const __half* srcB = g_wout;
    load_stage(As, Bs, srcA, srcB, 0, tid);
    load_stage(As + A_ST, Bs + B_ST, srcA, srcB, 1, tid);

    int warp = tid >> 5, lane = tid & 31;
    int wm = warp >> 1, wn = warp & 1;
    float acc[2][16][4];
    #pragma unroll
    for (int i = 0; i < 2; i++)
        #pragma unroll
        for (int j = 0; j < 16; j++)
            #pragma unroll
            for (int e = 0; e < 4; e++) acc[i][j][e] = 0.f;

    gemm_mainloop(acc, As, Bs, wm, wn, lane);

    int lr4 = lane >> 2, lc2 = (lane & 3) * 2;
    #pragma unroll
    for (int i = 0; i < 2; i++) {
        #pragma unroll
        for (int j = 0; j < 16; j++) {
            int col = wn * 128 + j * 8 + lc2;
            float bb0 = bout[col], bb1 = bout[col + 1];
            #pragma unroll
            for (int r = 0; r < 2; r++) {
                int rowg = bm * 128 + wm * 32 + i * 16 + lr4 + r * 8;
                int win = rowg >> 6, tok = rowg & 63;
                int b = win >> 6, w = win & 63;
                int wy = w >> 3, wx = w & 7;
                int ty = tok >> 3, tx = tok & 7;
                int gy = ((wy << 3) + ty + 4) & 63;
                int gx = ((wx << 3) + tx + 4) & 63;
                float2 v;
                v.x = acc[i][j][r * 2 + 0] + bb0;
                v.y = acc[i][j][r * 2 + 1] + bb1;
                *reinterpret_cast<float2*>(out + ((size_t)(b * 4096 + gy * 64 + gx)) * 256 + col) = v;
            }
        }
    }
}

// ---------------- launch ----------------
extern "C" void kernel_launch(void* const* d_in, const int* in_sizes, int n_in,
                              void* d_out, int out_size) {
    const float* x     = (const float*)d_in[0];
    const float* wqkv  = (const float*)d_in[1];
    const float* bqkv  = (const float*)d_in[2];
    const float* wout  = (const float*)d_in[3];
    const float* bout  = (const float*)d_in[4];
    const float* penc  = (const float*)d_in[5];
    float* out = (float*)d_out;

    const int SMEM_ATTN = 3 * 8 * 64 * LDW * 2 + 8 * 225 * 4 + 64 * 4;
    cudaFuncSetAttribute((const void*)qkv_gemm,   cudaFuncAttributeMaxDynamicSharedMemorySize, SMEM_GEMM2);
    cudaFuncSetAttribute((const void*)out_gemm,   cudaFuncAttributeMaxDynamicSharedMemorySize, SMEM_GEMM2);
    cudaFuncSetAttribute((const void*)attn_kernel, cudaFuncAttributeMaxDynamicSharedMemorySize, SMEM_ATTN);

    prep_weights<<<768, 256>>>(wqkv, wout);
    gather_x<<<WIN_TOT, 256>>>(x);
    qkv_gemm<<<dim3(3, 1024), 256, SMEM_GEMM2>>>(bqkv);
    attn_kernel<<<WIN_TOT, 512, SMEM_ATTN>>>(penc);
    out_gemm<<<1024, 256, SMEM_GEMM2>>>(bout, out);
}

// round 6
// speedup vs baseline: 1.1714x; 1.0162x over previous
#include <cuda_runtime.h>
#include <cuda_fp16.h>

// ---------------------------------------------------------------------------
// ShiftedWindowAttention: B=32, H=W=64, C=256, HEADS=8, HD=32, WS=8, SHIFT=4
// R5: fix attn smem-fill loop bound (256 int4, was 512 -> smem overflow).
//     attn -> per-(window,head) CTAs (64 thr, 16.5KB smem, high occupancy);
//     gather fused into qkv_gemm A-tile load.
// ---------------------------------------------------------------------------

#define WIN_TOT 2048
#define SCALE_F 0.17677669529663687f

__device__ __half g_q  [(size_t)WIN_TOT * 8 * 64 * 32];
__device__ __half g_k  [(size_t)WIN_TOT * 8 * 64 * 32];
__device__ __half g_v  [(size_t)WIN_TOT * 8 * 64 * 32];
__device__ __half g_att[(size_t)WIN_TOT * 64 * 256];
__device__ __half g_wqkv[768 * 256];
__device__ __half g_wout[256 * 256];

// ---------------- mma / ldmatrix helpers ----------------
__device__ __forceinline__ void mma_16816(float c[4], const unsigned a[4],
                                          unsigned b0, unsigned b1) {
    asm volatile(
        "mma.sync.aligned.m16n8k16.row.col.f32.f16.f16.f32 "
        "{%0,%1,%2,%3}, {%4,%5,%6,%7}, {%8,%9}, {%0,%1,%2,%3};\n"
        : "+f"(c[0]), "+f"(c[1]), "+f"(c[2]), "+f"(c[3])
        : "r"(a[0]), "r"(a[1]), "r"(a[2]), "r"(a[3]), "r"(b0), "r"(b1));
}
__device__ __forceinline__ void ldsm_x4(unsigned r[4], const __half* p) {
    unsigned addr = (unsigned)__cvta_generic_to_shared(p);
    asm volatile("ldmatrix.sync.aligned.m8n8.x4.shared.b16 {%0,%1,%2,%3}, [%4];"
                 : "=r"(r[0]), "=r"(r[1]), "=r"(r[2]), "=r"(r[3]) : "r"(addr));
}
__device__ __forceinline__ void ldsm_x4_t(unsigned r[4], const __half* p) {
    unsigned addr = (unsigned)__cvta_generic_to_shared(p);
    asm volatile("ldmatrix.sync.aligned.m8n8.x4.trans.shared.b16 {%0,%1,%2,%3}, [%4];"
                 : "=r"(r[0]), "=r"(r[1]), "=r"(r[2]), "=r"(r[3]) : "r"(addr));
}
__device__ __forceinline__ void ldfragA(unsigned r[4], const __half* t, int ld,
                                        int r0, int c0, int lane) {
    int lr = lane & 7, sel = lane >> 3;
    ldsm_x4(r, t + (r0 + lr + (sel & 1) * 8) * ld + c0 + ((sel >> 1) * 8));
}
__device__ __forceinline__ void ldfragB(unsigned r[4], const __half* t, int ld,
                                        int n0, int k0, int lane) {
    int lr = lane & 7, sel = lane >> 3;
    ldsm_x4(r, t + (n0 + lr + ((sel >> 1) * 8)) * ld + k0 + ((sel & 1) * 8));
}
__device__ __forceinline__ void ldfragBT(unsigned r[4], const __half* t, int ld,
                                         int k0, int n0, int lane) {
    int lr = lane & 7, sel = lane >> 3;
    ldsm_x4_t(r, t + (k0 + lr + ((sel & 1) * 8)) * ld + n0 + ((sel >> 1) * 8));
}
__device__ __forceinline__ unsigned packh2(float x, float y) {
    __half2 h = __floats2half2_rn(x, y);
    return *reinterpret_cast<unsigned*>(&h);
}
__device__ __forceinline__ void cp16(void* s, const void* g) {
    unsigned sa = (unsigned)__cvta_generic_to_shared(s);
    asm volatile("cp.async.cg.shared.global [%0], [%1], 16;" :: "r"(sa), "l"(g));
}
__device__ __forceinline__ void cp_commit() {
    asm volatile("cp.async.commit_group;");
}

// ---------------- prep ----------------
__global__ void prep_weights(const float* __restrict__ wqkv,
                             const float* __restrict__ wout) {
    int i = blockIdx.x * blockDim.x + threadIdx.x;
    if (i < 768 * 256) g_wqkv[i] = __float2half(wqkv[i]);
    if (i < 256 * 256) g_wout[i] = __float2half(wout[i]);
}

// ---------------- QKV GEMM with fused shifted-window gather ----------------
// CTA tile 128(M) x 256(N); A full-K in smem (gathered from x, fp32->fp16);
// B double-buffered via cp.async. grid (3, 1024): bn = q/k/v chunk.
#define LDA 264                 // A row pitch (halves)
#define LDB 136                 // B row pitch (halves)
#define A_HALVES (128 * LDA)    // 33792
#define B_ST (256 * LDB)        // 34816 per stage
#define SMEM_QKV ((A_HALVES + 2 * B_ST) * 2)   // 206848 bytes

__global__ __launch_bounds__(256, 1) void qkv_gemm(const float* __restrict__ x,
                                                   const float* __restrict__ bqkv) {
    extern __shared__ __half sm[];
    __half* As = sm;
    __half* Bs = sm + A_HALVES;
    int tid = threadIdx.x;
    int bn = blockIdx.x, bm = blockIdx.y;

    // kick off B loads first (async), both K-halves
    const __half* srcB = g_wqkv + (size_t)bn * 256 * 256;
    #pragma unroll
    for (int st = 0; st < 2; st++) {
        #pragma unroll
        for (int i = tid; i < 4096; i += 256) {
            int row = i >> 4, seg = i & 15;
            cp16(Bs + st * B_ST + row * LDB + seg * 8,
                 srcB + row * 256 + st * 128 + seg * 8);
        }
        cp_commit();
    }

    // gather A: 128 token rows, shifted-window indexed, fp32 -> fp16
    {
        int rowbase = bm * 128;
        #pragma unroll
        for (int i = tid; i < 128 * 64; i += 256) {   // 64 float4 per row
            int r = i >> 6, seg = i & 63;
            int rowg = rowbase + r;
            int win = rowg >> 6, tok = rowg & 63;
            int b = win >> 6, w = win & 63;
            int wy = w >> 3, wx = w & 7;
            int ty = tok >> 3, tx = tok & 7;
            int gy = ((wy << 3) + ty + 4) & 63;
            int gx = ((wx << 3) + tx + 4) & 63;
            float4 v = reinterpret_cast<const float4*>(
                x + ((size_t)(b * 4096 + gy * 64 + gx)) * 256)[seg];
            __half2* d2 = reinterpret_cast<__half2*>(As + r * LDA + seg * 4);
            d2[0] = __floats2half2_rn(v.x, v.y);
            d2[1] = __floats2half2_rn(v.z, v.w);
        }
    }

    int warp = tid >> 5, lane = tid & 31;
    int wm = warp >> 1, wn = warp & 1;
    float acc[2][16][4];
    #pragma unroll
    for (int i = 0; i < 2; i++)
        #pragma unroll
        for (int j = 0; j < 16; j++)
            #pragma unroll
            for (int e = 0; e < 4; e++) acc[i][j][e] = 0.f;

    #pragma unroll
    for (int st = 0; st < 2; st++) {
        if (st == 0) { asm volatile("cp.async.wait_group 1;"); }
        else         { asm volatile("cp.async.wait_group 0;"); }
        __syncthreads();
        const __half* Aw = As + (wm * 32) * LDA + st * 128;
        const __half* Bw = Bs + st * B_ST + (wn * 128) * LDB;
        #pragma unroll
        for (int kk = 0; kk < 8; kk++) {
            unsigned a0[4], a1[4];
            ldfragA(a0, Aw, LDA, 0,  kk * 16, lane);
            ldfragA(a1, Aw, LDA, 16, kk * 16, lane);
            #pragma unroll
            for (int j = 0; j < 8; j++) {
                unsigned b[4];
                ldfragB(b, Bw, LDB, j * 16, kk * 16, lane);
                mma_16816(acc[0][2 * j],     a0, b[0], b[1]);
                mma_16816(acc[0][2 * j + 1], a0, b[2], b[3]);
                mma_16816(acc[1][2 * j],     a1, b[0], b[1]);
                mma_16816(acc[1][2 * j + 1], a1, b[2], b[3]);
            }
        }
        __syncthreads();
    }

    __half* basep = (bn == 0) ? g_q : ((bn == 1) ? g_k : g_v);
    float scl = (bn == 0) ? SCALE_F : 1.0f;
    int lr4 = lane >> 2, lc2 = (lane & 3) * 2;
    #pragma unroll
    for (int i = 0; i < 2; i++) {
        #pragma unroll
        for (int j = 0; j < 16; j++) {
            int col = wn * 128 + j * 8 + lc2;
            int hd = col >> 5, d = col & 31;
            float bb0 = bqkv[bn * 256 + col], bb1 = bqkv[bn * 256 + col + 1];
            #pragma unroll
            for (int r = 0; r < 2; r++) {
                int rowg = bm * 128 + wm * 32 + i * 16 + lr4 + r * 8;
                int win = rowg >> 6, tok = rowg & 63;
                float v0 = (acc[i][j][r * 2 + 0] + bb0) * scl;
                float v1 = (acc[i][j][r * 2 + 1] + bb1) * scl;
                *reinterpret_cast<__half2*>(basep + (((size_t)(win * 8 + hd) * 64 + tok) * 32 + d)) =
                    __floats2half2_rn(v0, v1);
            }
        }
    }
}

// ---------------- attention: 1 CTA = (window, head), 2 warps ----------------
#define LDW 40
__global__ __launch_bounds__(64) void attn_kernel(const float* __restrict__ pos_enc) {
    __shared__ __half qs[64 * LDW];
    __shared__ __half ks[64 * LDW];
    __shared__ __half vs[64 * LDW];
    __shared__ float pe[225];
    __shared__ int rg[64];

    int tid = threadIdx.x;
    int h = blockIdx.x, win = blockIdx.y;
    int w = win & 63, wy = w >> 3, wx = w & 7;

    size_t base = ((size_t)win * 8 + h) * 64 * 32;
    const int4* gq = reinterpret_cast<const int4*>(g_q + base);
    const int4* gk = reinterpret_cast<const int4*>(g_k + base);
    const int4* gv = reinterpret_cast<const int4*>(g_v + base);
    #pragma unroll
    for (int i = tid; i < 256; i += 64) {      // 64 rows x 4 int4 each
        int row = i >> 2, s4 = i & 3;
        int doff = row * LDW + s4 * 8;
        *reinterpret_cast<int4*>(qs + doff) = gq[i];
        *reinterpret_cast<int4*>(ks + doff) = gk[i];
        *reinterpret_cast<int4*>(vs + doff) = gv[i];
    }
    #pragma unroll
    for (int i = tid; i < 225; i += 64) pe[i] = pos_enc[h * 225 + i];
    {
        int ty = tid >> 3, tx = tid & 7;
        int ry = (wy == 7) ? ((ty < 4) ? 1 : 2) : 0;
        int rx = (wx == 7) ? ((tx < 4) ? 1 : 2) : 0;
        rg[tid] = ry * 3 + rx;
    }
    __syncthreads();

    int warp = tid >> 5, lane = tid & 31;
    int lr4 = lane >> 2, lc2 = (lane & 3) * 2;

    #pragma unroll
    for (int si = 0; si < 2; si++) {
        int s = warp * 2 + si;
        float sa[8][4];
        #pragma unroll
        for (int nt = 0; nt < 8; nt++)
            #pragma unroll
            for (int e = 0; e < 4; e++) sa[nt][e] = 0.f;

        unsigned qa0[4], qa1[4];
        ldfragA(qa0, qs, LDW, s * 16, 0,  lane);
        ldfragA(qa1, qs, LDW, s * 16, 16, lane);
        #pragma unroll
        for (int np = 0; np < 4; np++) {
            unsigned kb0[4], kb1[4];
            ldfragB(kb0, ks, LDW, np * 16, 0,  lane);
            ldfragB(kb1, ks, LDW, np * 16, 16, lane);
            mma_16816(sa[2 * np],     qa0, kb0[0], kb0[1]);
            mma_16816(sa[2 * np + 1], qa0, kb0[2], kb0[3]);
            mma_16816(sa[2 * np],     qa1, kb1[0], kb1[1]);
            mma_16816(sa[2 * np + 1], qa1, kb1[2], kb1[3]);
        }

        int q0 = s * 16 + lr4, q1 = q0 + 8;
        int qy0 = q0 >> 3, qx0 = q0 & 7, qy1 = q1 >> 3, qx1 = q1 & 7;
        int r0 = rg[q0], r1 = rg[q1];
        float m0 = -1e30f, m1 = -1e30f;
        #pragma unroll
        for (int nt = 0; nt < 8; nt++) {
            #pragma unroll
            for (int e = 0; e < 2; e++) {
                int kc = nt * 8 + lc2 + e;
                int ky = kc >> 3, kx = kc & 7;
                int rk = rg[kc];
                float v = sa[nt][e] + pe[(qy0 - ky + 7) * 15 + (qx0 - kx + 7)];
                v = (rk != r0) ? -1e30f : v;
                sa[nt][e] = v; m0 = fmaxf(m0, v);
                float u = sa[nt][e + 2] + pe[(qy1 - ky + 7) * 15 + (qx1 - kx + 7)];
                u = (rk != r1) ? -1e30f : u;
                sa[nt][e + 2] = u; m1 = fmaxf(m1, u);
            }
        }
        m0 = fmaxf(m0, __shfl_xor_sync(0xffffffffu, m0, 1));
        m0 = fmaxf(m0, __shfl_xor_sync(0xffffffffu, m0, 2));
        m1 = fmaxf(m1, __shfl_xor_sync(0xffffffffu, m1, 1));
        m1 = fmaxf(m1, __shfl_xor_sync(0xffffffffu, m1, 2));
        float l0 = 0.f, l1 = 0.f;
        #pragma unroll
        for (int nt = 0; nt < 8; nt++) {
            #pragma unroll
            for (int e = 0; e < 2; e++) {
                float p  = __expf(sa[nt][e] - m0);     sa[nt][e] = p;      l0 += p;
                float q_ = __expf(sa[nt][e + 2] - m1); sa[nt][e + 2] = q_; l1 += q_;
            }
        }
        l0 += __shfl_xor_sync(0xffffffffu, l0, 1);
        l0 += __shfl_xor_sync(0xffffffffu, l0, 2);
        l1 += __shfl_xor_sync(0xffffffffu, l1, 1);
        l1 += __shfl_xor_sync(0xffffffffu, l1, 2);
        float il0 = 1.0f / l0, il1 = 1.0f / l1;

        float oa[4][4];
        #pragma unroll
        for (int j = 0; j < 4; j++)
            #pragma unroll
            for (int e = 0; e < 4; e++) oa[j][e] = 0.f;
        #pragma unroll
        for (int ksx = 0; ksx < 4; ksx++) {
            unsigned pa[4];
            pa[0] = packh2(sa[2 * ksx][0],     sa[2 * ksx][1]);
            pa[1] = packh2(sa[2 * ksx][2],     sa[2 * ksx][3]);
            pa[2] = packh2(sa[2 * ksx + 1][0], sa[2 * ksx + 1][1]);
            pa[3] = packh2(sa[2 * ksx + 1][2], sa[2 * ksx + 1][3]);
            unsigned vb[4];
            ldfragBT(vb, vs, LDW, ksx * 16, 0, lane);
            mma_16816(oa[0], pa, vb[0], vb[1]);
            mma_16816(oa[1], pa, vb[2], vb[3]);
            ldfragBT(vb, vs, LDW, ksx * 16, 16, lane);
            mma_16816(oa[2], pa, vb[0], vb[1]);
            mma_16816(oa[3], pa, vb[2], vb[3]);
        }
        #pragma unroll
        for (int j = 0; j < 4; j++) {
            int d = j * 8 + lc2;
            __half2 w0 = __floats2half2_rn(oa[j][0] * il0, oa[j][1] * il0);
            __half2 w1 = __floats2half2_rn(oa[j][2] * il1, oa[j][3] * il1);
            *reinterpret_cast<__half2*>(g_att + ((size_t)(win * 64 + q0) * 256) + h * 32 + d) = w0;
            *reinterpret_cast<__half2*>(g_att + ((size_t)(win * 64 + q1) * 256) + h * 32 + d) = w1;
        }
    }
}

// ---------------- out proj: 128x256 tile, cp.async 2-stage, scatter --------
#define A_ST2 (128 * LDB)
#define SMEM_OUT ((2 * A_ST2 + 2 * B_ST) * 2)   // 208896 bytes

__device__ __forceinline__ void load_stage_out(__half* As, __half* Bs,
                                               const __half* srcA, const __half* srcB,
                                               int st, int tid) {
    #pragma unroll
    for (int i = tid; i < 2048; i += 256) {
        int row = i >> 4, seg = i & 15;
        cp16(As + row * LDB + seg * 8, srcA + row * 256 + st * 128 + seg * 8);
    }
    #pragma unroll
    for (int i = tid; i < 4096; i += 256) {
        int row = i >> 4, seg = i & 15;
        cp16(Bs + row * LDB + seg * 8, srcB + row * 256 + st * 128 + seg * 8);
    }
    cp_commit();
}

__global__ __launch_bounds__(256, 1) void out_gemm(const float* __restrict__ bout,
                                                   float* __restrict__ out) {
    extern __shared__ __half sm[];
    __half* As = sm;
    __half* Bs = sm + 2 * A_ST2;
    int tid = threadIdx.x;
    int bm = blockIdx.x;

    const __half* srcA = g_att + (size_t)bm * 128 * 256;
    const __half* srcB = g_wout;
    load_stage_out(As, Bs, srcA, srcB, 0, tid);
    load_stage_out(As + A_ST2, Bs + B_ST, srcA, srcB, 1, tid);

    int warp = tid >> 5, lane = tid & 31;
    int wm = warp >> 1, wn = warp & 1;
    float acc[2][16][4];
    #pragma unroll
    for (int i = 0; i < 2; i++)
        #pragma unroll
        for (int j = 0; j < 16; j++)
            #pragma unroll
            for (int e = 0; e < 4; e++) acc[i][j][e] = 0.f;

    #pragma unroll
    for (int st = 0; st < 2; st++) {
        if (st == 0) { asm volatile("cp.async.wait_group 1;"); }
        else         { asm volatile("cp.async.wait_group 0;"); }
        __syncthreads();
        const __half* Aw = As + st * A_ST2 + (wm * 32) * LDB;
        const __half* Bw = Bs + st * B_ST + (wn * 128) * LDB;
        #pragma unroll
        for (int kk = 0; kk < 8; kk++) {
            unsigned a0[4], a1[4];
            ldfragA(a0, Aw, LDB, 0,  kk * 16, lane);
            ldfragA(a1, Aw, LDB, 16, kk * 16, lane);
            #pragma unroll
            for (int j = 0; j < 8; j++) {
                unsigned b[4];
                ldfragB(b, Bw, LDB, j * 16, kk * 16, lane);
                mma_16816(acc[0][2 * j],     a0, b[0], b[1]);
                mma_16816(acc[0][2 * j + 1], a0, b[2], b[3]);
                mma_16816(acc[1][2 * j],     a1, b[0], b[1]);
                mma_16816(acc[1][2 * j + 1], a1, b[2], b[3]);
            }
        }
        __syncthreads();
    }

    int lr4 = lane >> 2, lc2 = (lane & 3) * 2;
    #pragma unroll
    for (int i = 0; i < 2; i++) {
        #pragma unroll
        for (int j = 0; j < 16; j++) {
            int col = wn * 128 + j * 8 + lc2;
            float bb0 = bout[col], bb1 = bout[col + 1];
            #pragma unroll
            for (int r = 0; r < 2; r++) {
                int rowg = bm * 128 + wm * 32 + i * 16 + lr4 + r * 8;
                int win = rowg >> 6, tok = rowg & 63;
                int b = win >> 6, w = win & 63;
                int wy = w >> 3, wx = w & 7;
                int ty = tok >> 3, tx = tok & 7;
                int gy = ((wy << 3) + ty + 4) & 63;
                int gx = ((wx << 3) + tx + 4) & 63;
                float2 v;
                v.x = acc[i][j][r * 2 + 0] + bb0;
                v.y = acc[i][j][r * 2 + 1] + bb1;
                *reinterpret_cast<float2*>(out + ((size_t)(b * 4096 + gy * 64 + gx)) * 256 + col) = v;
            }
        }
    }
}

// ---------------- launch ----------------
extern "C" void kernel_launch(void* const* d_in, const int* in_sizes, int n_in,
                              void* d_out, int out_size) {
    const float* x     = (const float*)d_in[0];
    const float* wqkv  = (const float*)d_in[1];
    const float* bqkv  = (const float*)d_in[2];
    const float* wout  = (const float*)d_in[3];
    const float* bout  = (const float*)d_in[4];
    const float* penc  = (const float*)d_in[5];
    float* out = (float*)d_out;

    cudaFuncSetAttribute((const void*)qkv_gemm, cudaFuncAttributeMaxDynamicSharedMemorySize, SMEM_QKV);
    cudaFuncSetAttribute((const void*)out_gemm, cudaFuncAttributeMaxDynamicSharedMemorySize, SMEM_OUT);

    prep_weights<<<768, 256>>>(wqkv, wout);
    qkv_gemm<<<dim3(3, 1024), 256, SMEM_QKV>>>(x, bqkv);
    attn_kernel<<<dim3(8, WIN_TOT), 64>>>(penc);
    out_gemm<<<1024, 256, SMEM_OUT>>>(bout, out);
}

// round 7
// speedup vs baseline: 1.4491x; 1.2371x over previous
#include <cuda_runtime.h>
#include <cuda_fp16.h>

// ---------------------------------------------------------------------------
// ShiftedWindowAttention: B=32, H=W=64, C=256, HEADS=8, HD=32, WS=8, SHIFT=4
// R6: projection GEMMs rebuilt: stationary operand (64KB, 4 K-panels, xor-
//     swizzled) + streamed operand (16KB stages, cp.async double buffer,
//     1-stage lookahead). 96KB smem, 64-acc warps -> 2 CTAs/SM.
//     qkv reads x ONCE (grid bm only, all 6 N-tiles per CTA).
// ---------------------------------------------------------------------------

#define WIN_TOT 2048
#define SCALE_F 0.17677669529663687f
#define PANEL 8192              // halves per 128x64 tile (16KB)

__device__ __half g_q  [(size_t)WIN_TOT * 8 * 64 * 32];
__device__ __half g_k  [(size_t)WIN_TOT * 8 * 64 * 32];
__device__ __half g_v  [(size_t)WIN_TOT * 8 * 64 * 32];
__device__ __half g_att[(size_t)WIN_TOT * 64 * 256];
__device__ __half g_wqkv[768 * 256];
__device__ __half g_wout[256 * 256];

// ---------------- mma / ldmatrix helpers ----------------
__device__ __forceinline__ void mma_16816(float c[4], const unsigned a[4],
                                          unsigned b0, unsigned b1) {
    asm volatile(
        "mma.sync.aligned.m16n8k16.row.col.f32.f16.f16.f32 "
        "{%0,%1,%2,%3}, {%4,%5,%6,%7}, {%8,%9}, {%0,%1,%2,%3};\n"
        : "+f"(c[0]), "+f"(c[1]), "+f"(c[2]), "+f"(c[3])
        : "r"(a[0]), "r"(a[1]), "r"(a[2]), "r"(a[3]), "r"(b0), "r"(b1));
}
__device__ __forceinline__ void ldsm_x4(unsigned r[4], const __half* p) {
    unsigned addr = (unsigned)__cvta_generic_to_shared(p);
    asm volatile("ldmatrix.sync.aligned.m8n8.x4.shared.b16 {%0,%1,%2,%3}, [%4];"
                 : "=r"(r[0]), "=r"(r[1]), "=r"(r[2]), "=r"(r[3]) : "r"(addr));
}
__device__ __forceinline__ void ldsm_x4_t(unsigned r[4], const __half* p) {
    unsigned addr = (unsigned)__cvta_generic_to_shared(p);
    asm volatile("ldmatrix.sync.aligned.m8n8.x4.trans.shared.b16 {%0,%1,%2,%3}, [%4];"
                 : "=r"(r[0]), "=r"(r[1]), "=r"(r[2]), "=r"(r[3]) : "r"(addr));
}
// Swizzled tiles: 64-half (128B) rows, 16B chunk c stored at c ^ (row & 7).
__device__ __forceinline__ const __half* swaddr(const __half* base, int row, int colh) {
    return base + row * 64 + ((((colh >> 3) ^ (row & 7))) << 3);
}
// A fragment (row-major MxK): matrices (m0,k0)(m0+8,k0)(m0,k0+8)(m0+8,k0+8)
__device__ __forceinline__ void ldA_sw(unsigned r[4], const __half* base,
                                       int r0, int c0, int lane) {
    int lr = lane & 7, sel = lane >> 3;
    ldsm_x4(r, swaddr(base, r0 + lr + (sel & 1) * 8, c0 + ((sel >> 1) * 8)));
}
// B fragment ([N][K] rows): two n-tiles (n0 in regs 0,1; n0+8 in regs 2,3)
__device__ __forceinline__ void ldB_sw(unsigned r[4], const __half* base,
                                       int n0, int k0, int lane) {
    int lr = lane & 7, sel = lane >> 3;
    ldsm_x4(r, swaddr(base, n0 + lr + ((sel >> 1) * 8), k0 + ((sel & 1) * 8)));
}
// Unswizzled variants (attention tiles, LDW pitch)
__device__ __forceinline__ void ldfragA(unsigned r[4], const __half* t, int ld,
                                        int r0, int c0, int lane) {
    int lr = lane & 7, sel = lane >> 3;
    ldsm_x4(r, t + (r0 + lr + (sel & 1) * 8) * ld + c0 + ((sel >> 1) * 8));
}
__device__ __forceinline__ void ldfragB(unsigned r[4], const __half* t, int ld,
                                        int n0, int k0, int lane) {
    int lr = lane & 7, sel = lane >> 3;
    ldsm_x4(r, t + (n0 + lr + ((sel >> 1) * 8)) * ld + k0 + ((sel & 1) * 8));
}
__device__ __forceinline__ void ldfragBT(unsigned r[4], const __half* t, int ld,
                                         int k0, int n0, int lane) {
    int lr = lane & 7, sel = lane >> 3;
    ldsm_x4_t(r, t + (k0 + lr + ((sel & 1) * 8)) * ld + n0 + ((sel >> 1) * 8));
}
__device__ __forceinline__ unsigned packh2(float x, float y) {
    __half2 h = __floats2half2_rn(x, y);
    return *reinterpret_cast<unsigned*>(&h);
}
__device__ __forceinline__ void cp16(void* s, const void* g) {
    unsigned sa = (unsigned)__cvta_generic_to_shared(s);
    asm volatile("cp.async.cg.shared.global [%0], [%1], 16;" :: "r"(sa), "l"(g));
}
__device__ __forceinline__ void cp_commit() {
    asm volatile("cp.async.commit_group;");
}

// ---------------- prep ----------------
__global__ void prep_weights(const float* __restrict__ wqkv,
                             const float* __restrict__ wout) {
    int i = blockIdx.x * blockDim.x + threadIdx.x;
    if (i < 768 * 256) g_wqkv[i] = __float2half(wqkv[i]);
    if (i < 256 * 256) g_wout[i] = __float2half(wout[i]);
}

// ---------------- QKV GEMM: x read once; A stationary, B streamed ----------
// grid (1024): bm. Per CTA: A = gathered 128x256 (4 panels). Loop nt=0..5
// over N-tiles of 128 (q0 q1 k0 k1 v0 v1); B stages (nt,kt) of 128x64
// cp.async double-buffered. 8 warps: wm=warp>>1 (A rows), wn=warp&1 (B rows).
#define SMEM_PROJ (6 * PANEL * 2)   // 98304 bytes

__global__ __launch_bounds__(256, 2) void qkv_gemm(const float* __restrict__ x,
                                                   const float* __restrict__ bqkv) {
    extern __shared__ __half sm[];
    __half* Ast  = sm;               // 4 panels stationary
    __half* Bbuf = sm + 4 * PANEL;   // 2 streamed buffers
    int tid = threadIdx.x, bm = blockIdx.x;

    // prologue: B stages 0,1 (nt=0, kt=0/1) async
    #pragma unroll
    for (int s = 0; s < 2; s++) {
        #pragma unroll
        for (int i = tid; i < 1024; i += 256) {
            int r = i >> 3, c = i & 7;
            cp16(Bbuf + s * PANEL + r * 64 + ((c ^ (r & 7)) * 8),
                 g_wqkv + (size_t)r * 256 + s * 64 + c * 8);
        }
        cp_commit();
    }

    // stationary A: shifted-window gather, fp32 -> fp16, 4 swizzled panels
    for (int i = tid; i < 4096; i += 256) {
        int r = i >> 5, ch = i & 31, p = ch >> 3, c = ch & 7;
        int rowg = bm * 128 + r;
        int win = rowg >> 6, tok = rowg & 63;
        int b = win >> 6, w = win & 63;
        int gy = (((w >> 3) << 3) + (tok >> 3) + 4) & 63;
        int gx = (((w & 7) << 3) + (tok & 7) + 4) & 63;
        const float4* src = reinterpret_cast<const float4*>(
            x + ((size_t)(b * 4096 + gy * 64 + gx)) * 256) + p * 16 + c * 2;
        float4 v0 = src[0], v1 = src[1];
        __half2* d2 = reinterpret_cast<__half2*>(
            Ast + p * PANEL + r * 64 + ((c ^ (r & 7)) * 8));
        d2[0] = __floats2half2_rn(v0.x, v0.y);
        d2[1] = __floats2half2_rn(v0.z, v0.w);
        d2[2] = __floats2half2_rn(v1.x, v1.y);
        d2[3] = __floats2half2_rn(v1.z, v1.w);
    }

    int warp = tid >> 5, lane = tid & 31;
    int wm = warp >> 1, wn = warp & 1;
    int lr4 = lane >> 2, lc2 = (lane & 3) * 2;
    int bufc = 0;

    for (int nt = 0; nt < 6; nt++) {
        float acc[2][8][4];
        #pragma unroll
        for (int i = 0; i < 2; i++)
            #pragma unroll
            for (int j = 0; j < 8; j++)
                #pragma unroll
                for (int e = 0; e < 4; e++) acc[i][j][e] = 0.f;

        for (int kt = 0; kt < 4; kt++) {
            int ss = nt * 4 + kt;
            if (ss < 23) { asm volatile("cp.async.wait_group 1;"); }
            else         { asm volatile("cp.async.wait_group 0;"); }
            __syncthreads();
            const __half* Ap = Ast + kt * PANEL;
            const __half* Bp = Bbuf + bufc * PANEL;
            #pragma unroll
            for (int kk = 0; kk < 4; kk++) {
                unsigned a0[4], a1[4];
                ldA_sw(a0, Ap, wm * 32,      kk * 16, lane);
                ldA_sw(a1, Ap, wm * 32 + 16, kk * 16, lane);
                #pragma unroll
                for (int j = 0; j < 4; j++) {
                    unsigned b[4];
                    ldB_sw(b, Bp, wn * 64 + j * 16, kk * 16, lane);
                    mma_16816(acc[0][2 * j],     a0, b[0], b[1]);
                    mma_16816(acc[0][2 * j + 1], a0, b[2], b[3]);
                    mma_16816(acc[1][2 * j],     a1, b[0], b[1]);
                    mma_16816(acc[1][2 * j + 1], a1, b[2], b[3]);
                }
            }
            __syncthreads();
            int nss = ss + 2;
            if (nss < 24) {
                int nnt = nss >> 2, nkt = nss & 3;
                #pragma unroll
                for (int i = tid; i < 1024; i += 256) {
                    int r = i >> 3, c = i & 7;
                    cp16(Bbuf + bufc * PANEL + r * 64 + ((c ^ (r & 7)) * 8),
                         g_wqkv + (size_t)(nnt * 128 + r) * 256 + nkt * 64 + c * 8);
                }
                cp_commit();
            }
            bufc ^= 1;
        }

        // epilogue for this N-tile (overlaps with next tile's loads)
        int which = nt >> 1;
        __half* basep = (which == 0) ? g_q : ((which == 1) ? g_k : g_v);
        float scl = (which == 0) ? SCALE_F : 1.0f;
        #pragma unroll
        for (int i = 0; i < 2; i++) {
            #pragma unroll
            for (int j = 0; j < 8; j++) {
                int c256 = (nt & 1) * 128 + wn * 64 + j * 8 + lc2;
                int hd = c256 >> 5, d = c256 & 31;
                float bb0 = bqkv[which * 256 + c256];
                float bb1 = bqkv[which * 256 + c256 + 1];
                #pragma unroll
                for (int r = 0; r < 2; r++) {
                    int rowg = bm * 128 + wm * 32 + i * 16 + lr4 + r * 8;
                    int win = rowg >> 6, tok = rowg & 63;
                    float v0 = (acc[i][j][r * 2 + 0] + bb0) * scl;
                    float v1 = (acc[i][j][r * 2 + 1] + bb1) * scl;
                    *reinterpret_cast<__half2*>(
                        basep + (((size_t)(win * 8 + hd) * 64 + tok) * 32 + d)) =
                        __floats2half2_rn(v0, v1);
                }
            }
        }
    }
}

// ---------------- attention: 1 CTA = (window, head), 2 warps ----------------
#define LDW 40
__global__ __launch_bounds__(64) void attn_kernel(const float* __restrict__ pos_enc) {
    __shared__ __half qs[64 * LDW];
    __shared__ __half ks[64 * LDW];
    __shared__ __half vs[64 * LDW];
    __shared__ float pe[225];
    __shared__ int rg[64];

    int tid = threadIdx.x;
    int h = blockIdx.x, win = blockIdx.y;
    int w = win & 63, wy = w >> 3, wx = w & 7;

    size_t base = ((size_t)win * 8 + h) * 64 * 32;
    const int4* gq = reinterpret_cast<const int4*>(g_q + base);
    const int4* gk = reinterpret_cast<const int4*>(g_k + base);
    const int4* gv = reinterpret_cast<const int4*>(g_v + base);
    #pragma unroll
    for (int i = tid; i < 256; i += 64) {      // 64 rows x 4 int4 each
        int row = i >> 2, s4 = i & 3;
        int doff = row * LDW + s4 * 8;
        *reinterpret_cast<int4*>(qs + doff) = gq[i];
        *reinterpret_cast<int4*>(ks + doff) = gk[i];
        *reinterpret_cast<int4*>(vs + doff) = gv[i];
    }
    #pragma unroll
    for (int i = tid; i < 225; i += 64) pe[i] = pos_enc[h * 225 + i];
    {
        int ty = tid >> 3, tx = tid & 7;
        int ry = (wy == 7) ? ((ty < 4) ? 1 : 2) : 0;
        int rx = (wx == 7) ? ((tx < 4) ? 1 : 2) : 0;
        rg[tid] = ry * 3 + rx;
    }
    __syncthreads();

    int warp = tid >> 5, lane = tid & 31;
    int lr4 = lane >> 2, lc2 = (lane & 3) * 2;

    #pragma unroll
    for (int si = 0; si < 2; si++) {
        int s = warp * 2 + si;
        float sa[8][4];
        #pragma unroll
        for (int nt = 0; nt < 8; nt++)
            #pragma unroll
            for (int e = 0; e < 4; e++) sa[nt][e] = 0.f;

        unsigned qa0[4], qa1[4];
        ldfragA(qa0, qs, LDW, s * 16, 0,  lane);
        ldfragA(qa1, qs, LDW, s * 16, 16, lane);
        #pragma unroll
        for (int np = 0; np < 4; np++) {
            unsigned kb0[4], kb1[4];
            ldfragB(kb0, ks, LDW, np * 16, 0,  lane);
            ldfragB(kb1, ks, LDW, np * 16, 16, lane);
            mma_16816(sa[2 * np],     qa0, kb0[0], kb0[1]);
            mma_16816(sa[2 * np + 1], qa0, kb0[2], kb0[3]);
            mma_16816(sa[2 * np],     qa1, kb1[0], kb1[1]);
            mma_16816(sa[2 * np + 1], qa1, kb1[2], kb1[3]);
        }

        int q0 = s * 16 + lr4, q1 = q0 + 8;
        int qy0 = q0 >> 3, qx0 = q0 & 7, qy1 = q1 >> 3, qx1 = q1 & 7;
        int r0 = rg[q0], r1 = rg[q1];
        float m0 = -1e30f, m1 = -1e30f;
        #pragma unroll
        for (int nt = 0; nt < 8; nt++) {
            #pragma unroll
            for (int e = 0; e < 2; e++) {
                int kc = nt * 8 + lc2 + e;
                int ky = kc >> 3, kx = kc & 7;
                int rk = rg[kc];
                float v = sa[nt][e] + pe[(qy0 - ky + 7) * 15 + (qx0 - kx + 7)];
                v = (rk != r0) ? -1e30f : v;
                sa[nt][e] = v; m0 = fmaxf(m0, v);
                float u = sa[nt][e + 2] + pe[(qy1 - ky + 7) * 15 + (qx1 - kx + 7)];
                u = (rk != r1) ? -1e30f : u;
                sa[nt][e + 2] = u; m1 = fmaxf(m1, u);
            }
        }
        m0 = fmaxf(m0, __shfl_xor_sync(0xffffffffu, m0, 1));
        m0 = fmaxf(m0, __shfl_xor_sync(0xffffffffu, m0, 2));
        m1 = fmaxf(m1, __shfl_xor_sync(0xffffffffu, m1, 1));
        m1 = fmaxf(m1, __shfl_xor_sync(0xffffffffu, m1, 2));
        float l0 = 0.f, l1 = 0.f;
        #pragma unroll
        for (int nt = 0; nt < 8; nt++) {
            #pragma unroll
            for (int e = 0; e < 2; e++) {
                float p  = __expf(sa[nt][e] - m0);     sa[nt][e] = p;      l0 += p;
                float q_ = __expf(sa[nt][e + 2] - m1); sa[nt][e + 2] = q_; l1 += q_;
            }
        }
        l0 += __shfl_xor_sync(0xffffffffu, l0, 1);
        l0 += __shfl_xor_sync(0xffffffffu, l0, 2);
        l1 += __shfl_xor_sync(0xffffffffu, l1, 1);
        l1 += __shfl_xor_sync(0xffffffffu, l1, 2);
        float il0 = 1.0f / l0, il1 = 1.0f / l1;

        float oa[4][4];
        #pragma unroll
        for (int j = 0; j < 4; j++)
            #pragma unroll
            for (int e = 0; e < 4; e++) oa[j][e] = 0.f;
        #pragma unroll
        for (int ksx = 0; ksx < 4; ksx++) {
            unsigned pa[4];
            pa[0] = packh2(sa[2 * ksx][0],     sa[2 * ksx][1]);
            pa[1] = packh2(sa[2 * ksx][2],     sa[2 * ksx][3]);
            pa[2] = packh2(sa[2 * ksx + 1][0], sa[2 * ksx + 1][1]);
            pa[3] = packh2(sa[2 * ksx + 1][2], sa[2 * ksx + 1][3]);
            unsigned vb[4];
            ldfragBT(vb, vs, LDW, ksx * 16, 0, lane);
            mma_16816(oa[0], pa, vb[0], vb[1]);
            mma_16816(oa[1], pa, vb[2], vb[3]);
            ldfragBT(vb, vs, LDW, ksx * 16, 16, lane);
            mma_16816(oa[2], pa, vb[0], vb[1]);
            mma_16816(oa[3], pa, vb[2], vb[3]);
        }
        #pragma unroll
        for (int j = 0; j < 4; j++) {
            int d = j * 8 + lc2;
            __half2 w0 = __floats2half2_rn(oa[j][0] * il0, oa[j][1] * il0);
            __half2 w1 = __floats2half2_rn(oa[j][2] * il1, oa[j][3] * il1);
            *reinterpret_cast<__half2*>(g_att + ((size_t)(win * 64 + q0) * 256) + h * 32 + d) = w0;
            *reinterpret_cast<__half2*>(g_att + ((size_t)(win * 64 + q1) * 256) + h * 32 + d) = w1;
        }
    }
}

// ---------------- out proj: B stationary, A streamed; merge+roll scatter ---
// grid (1024, 2): bm, bn(=128 output channels each).
__global__ __launch_bounds__(256, 2) void out_gemm(const float* __restrict__ bout,
                                                   float* __restrict__ out) {
    extern __shared__ __half sm2[];
    __half* Bst  = sm2;              // 4 panels stationary (wout slice)
    __half* Abuf = sm2 + 4 * PANEL;  // 2 streamed buffers (g_att)
    int tid = threadIdx.x, bm = blockIdx.x, bn = blockIdx.y;

    // prologue: A stages 0,1 async
    #pragma unroll
    for (int s = 0; s < 2; s++) {
        #pragma unroll
        for (int i = tid; i < 1024; i += 256) {
            int r = i >> 3, c = i & 7;
            cp16(Abuf + s * PANEL + r * 64 + ((c ^ (r & 7)) * 8),
                 g_att + (size_t)(bm * 128 + r) * 256 + s * 64 + c * 8);
        }
        cp_commit();
    }
    // stationary B (sync copy; overlaps with in-flight A cp.async)
    for (int i = tid; i < 4096; i += 256) {
        int r = i >> 5, ch = i & 31, p = ch >> 3, c = ch & 7;
        int4 v = *reinterpret_cast<const int4*>(
            g_wout + (size_t)(bn * 128 + r) * 256 + p * 64 + c * 8);
        *reinterpret_cast<int4*>(Bst + p * PANEL + r * 64 + ((c ^ (r & 7)) * 8)) = v;
    }

    int warp = tid >> 5, lane = tid & 31;
    int wm = warp >> 1, wn = warp & 1;
    float acc[2][8][4];
    #pragma unroll
    for (int i = 0; i < 2; i++)
        #pragma unroll
        for (int j = 0; j < 8; j++)
            #pragma unroll
            for (int e = 0; e < 4; e++) acc[i][j][e] = 0.f;

    int bufc = 0;
    for (int kt = 0; kt < 4; kt++) {
        if (kt < 3) { asm volatile("cp.async.wait_group 1;"); }
        else        { asm volatile("cp.async.wait_group 0;"); }
        __syncthreads();
        const __half* Ap = Abuf + bufc * PANEL;
        const __half* Bp = Bst + kt * PANEL;
        #pragma unroll
        for (int kk = 0; kk < 4; kk++) {
            unsigned a0[4], a1[4];
            ldA_sw(a0, Ap, wm * 32,      kk * 16, lane);
            ldA_sw(a1, Ap, wm * 32 + 16, kk * 16, lane);
            #pragma unroll
            for (int j = 0; j < 4; j++) {
                unsigned b[4];
                ldB_sw(b, Bp, wn * 64 + j * 16, kk * 16, lane);
                mma_16816(acc[0][2 * j],     a0, b[0], b[1]);
                mma_16816(acc[0][2 * j + 1], a0, b[2], b[3]);
                mma_16816(acc[1][2 * j],     a1, b[0], b[1]);
                mma_16816(acc[1][2 * j + 1], a1, b[2], b[3]);
            }
        }
        __syncthreads();
        int nkt = kt + 2;
        if (nkt < 4) {
            #pragma unroll
            for (int i = tid; i < 1024; i += 256) {
                int r = i >> 3, c = i & 7;
                cp16(Abuf + bufc * PANEL + r * 64 + ((c ^ (r & 7)) * 8),
                     g_att + (size_t)(bm * 128 + r) * 256 + nkt * 64 + c * 8);
            }
            cp_commit();
        }
        bufc ^= 1;
    }

    int lr4 = lane >> 2, lc2 = (lane & 3) * 2;
    #pragma unroll
    for (int i = 0; i < 2; i++) {
        #pragma unroll
        for (int j = 0; j < 8; j++) {
            int col = bn * 128 + wn * 64 + j * 8 + lc2;
            float bb0 = bout[col], bb1 = bout[col + 1];
            #pragma unroll
            for (int r = 0; r < 2; r++) {
                int rowg = bm * 128 + wm * 32 + i * 16 + lr4 + r * 8;
                int win = rowg >> 6, tok = rowg & 63;
                int b = win >> 6, w = win & 63;
                int wy = w >> 3, wx = w & 7;
                int ty = tok >> 3, tx = tok & 7;
                int gy = ((wy << 3) + ty + 4) & 63;
                int gx = ((wx << 3) + tx + 4) & 63;
                float2 v;
                v.x = acc[i][j][r * 2 + 0] + bb0;
                v.y = acc[i][j][r * 2 + 1] + bb1;
                *reinterpret_cast<float2*>(
                    out + ((size_t)(b * 4096 + gy * 64 + gx)) * 256 + col) = v;
            }
        }
    }
}

// ---------------- launch ----------------
extern "C" void kernel_launch(void* const* d_in, const int* in_sizes, int n_in,
                              void* d_out, int out_size) {
    const float* x     = (const float*)d_in[0];
    const float* wqkv  = (const float*)d_in[1];
    const float* bqkv  = (const float*)d_in[2];
    const float* wout  = (const float*)d_in[3];
    const float* bout  = (const float*)d_in[4];
    const float* penc  = (const float*)d_in[5];
    float* out = (float*)d_out;

    cudaFuncSetAttribute((const void*)qkv_gemm, cudaFuncAttributeMaxDynamicSharedMemorySize, SMEM_PROJ);
    cudaFuncSetAttribute((const void*)out_gemm, cudaFuncAttributeMaxDynamicSharedMemorySize, SMEM_PROJ);

    prep_weights<<<768, 256>>>(wqkv, wout);
    qkv_gemm<<<1024, 256, SMEM_PROJ>>>(x, bqkv);
    attn_kernel<<<dim3(8, WIN_TOT), 64>>>(penc);
    out_gemm<<<dim3(1024, 2), 256, SMEM_PROJ>>>(bout, out);
}